// round 1
// baseline (speedup 1.0000x reference)
#include <cuda_runtime.h>
#include <math.h>

// Problem constants (from reference: B=2, T=16, N=1024, D=3)
#define BT     32
#define NPTS   1024
#define TPB    256
#define CHUNKS (NPTS / TPB)          // 4
#define NBLOCKS (BT * CHUNKS)        // 128
#define EPS    1e-6f

// Scratch for deterministic two-stage reduction (no cudaMalloc allowed).
__device__ float g_partials[NBLOCKS];

// Main kernel: one block handles (batch bt, chunk c). It loads the full x and
// y point sets of the batch into shared memory as float4 (x, y, z, 0.5*||p||^2),
// then each thread computes:
//   min1 for x-point  pid = c*TPB + tid   (min over all y)
//   min2 for y-point  pid                  (min over all x)
// using the identity  sq_ij = 2*(P.w - (P.xyz . Q.xyz - Q.w))
// so the inner loop is 3 FFMA + 1 FMNMX per pair per direction.
__global__ void __launch_bounds__(TPB, 1)
chamfer_main_kernel(const float* __restrict__ x, const float* __restrict__ y) {
    __shared__ float4 sx[NPTS];
    __shared__ float4 sy[NPTS];

    const int bt    = blockIdx.x / CHUNKS;
    const int chunk = blockIdx.x % CHUNKS;
    const float* xb = x + (size_t)bt * NPTS * 3;
    const float* yb = y + (size_t)bt * NPTS * 3;

    // Stage point sets into smem with precomputed half-norms.
    for (int p = threadIdx.x; p < NPTS; p += TPB) {
        float a0 = xb[3 * p + 0];
        float a1 = xb[3 * p + 1];
        float a2 = xb[3 * p + 2];
        float ha = 0.5f * (a0 * a0 + a1 * a1 + a2 * a2);
        sx[p] = make_float4(a0, a1, a2, ha);

        float b0 = yb[3 * p + 0];
        float b1 = yb[3 * p + 1];
        float b2 = yb[3 * p + 2];
        float hb = 0.5f * (b0 * b0 + b1 * b1 + b2 * b2);
        sy[p] = make_float4(b0, b1, b2, hb);
    }
    __syncthreads();

    const int pid = chunk * TPB + threadIdx.x;
    const float4 P = sx[pid];   // x-point for min1 direction
    const float4 Q = sy[pid];   // y-point for min2 direction

    float m1 = -INFINITY;       // max over i of (P . y_i - 0.5*||y_i||^2)
    float m2 = -INFINITY;       // max over j of (Q . x_j - 0.5*||x_j||^2)

    // Uniform loop index across the warp -> LDS.128 broadcast, conflict-free.
#pragma unroll 8
    for (int i = 0; i < NPTS; ++i) {
        float4 Y = sy[i];
        float t = fmaf(P.z, Y.z, -Y.w);
        t = fmaf(P.y, Y.y, t);
        t = fmaf(P.x, Y.x, t);
        m1 = fmaxf(m1, t);

        float4 X = sx[i];
        float u = fmaf(Q.z, X.z, -X.w);
        u = fmaf(Q.y, X.y, u);
        u = fmaf(Q.x, X.x, u);
        m2 = fmaxf(m2, u);
    }

    // min over i of sq = 2*(P.w - m1); clamp at 0, then dist = sqrt(EPS + sq).
    float sq1 = fmaxf(2.0f * (P.w - m1), 0.0f);
    float sq2 = fmaxf(2.0f * (Q.w - m2), 0.0f);
    float contrib = sqrtf(EPS + sq1) + sqrtf(EPS + sq2);

    // Block reduction: warp shfl, then smem across the 8 warps.
    __shared__ float warp_sums[TPB / 32];
    float v = contrib;
#pragma unroll
    for (int off = 16; off > 0; off >>= 1)
        v += __shfl_down_sync(0xFFFFFFFFu, v, off);
    if ((threadIdx.x & 31) == 0)
        warp_sums[threadIdx.x >> 5] = v;
    __syncthreads();
    if (threadIdx.x == 0) {
        float s = 0.0f;
#pragma unroll
        for (int w = 0; w < TPB / 32; ++w)
            s += warp_sums[w];
        g_partials[blockIdx.x] = s;
    }
}

// Final reduction: deterministic, one block.
__global__ void chamfer_reduce_kernel(float* __restrict__ out) {
    __shared__ float warp_sums[NBLOCKS / 32];
    float v = g_partials[threadIdx.x];
#pragma unroll
    for (int off = 16; off > 0; off >>= 1)
        v += __shfl_down_sync(0xFFFFFFFFu, v, off);
    if ((threadIdx.x & 31) == 0)
        warp_sums[threadIdx.x >> 5] = v;
    __syncthreads();
    if (threadIdx.x == 0) {
        float s = 0.0f;
#pragma unroll
        for (int w = 0; w < NBLOCKS / 32; ++w)
            s += warp_sums[w];
        // mean(min1) + mean(min2); both means over BT*NPTS values.
        out[0] = s * (1.0f / (float)(BT * NPTS));
    }
}

extern "C" void kernel_launch(void* const* d_in, const int* in_sizes, int n_in,
                              void* d_out, int out_size) {
    const float* x = (const float*)d_in[0];
    const float* y = (const float*)d_in[1];
    float* out = (float*)d_out;
    (void)in_sizes; (void)n_in; (void)out_size;

    chamfer_main_kernel<<<NBLOCKS, TPB>>>(x, y);
    chamfer_reduce_kernel<<<1, NBLOCKS>>>(out);
}

// round 2
// speedup vs baseline: 1.1735x; 1.1735x over previous
#include <cuda_runtime.h>
#include <math.h>

// Problem constants (B=2, T=16, N=1024, D=3)
#define BT      32
#define NPTS    1024
#define NPAIRS  (NPTS / 2)
#define TPB     256
#define CHUNKS  (NPTS / TPB)          // 4
#define NBLOCKS (BT * CHUNKS)         // 128
#define EPS     1e-6f

__device__ float        g_partials[NBLOCKS];
__device__ unsigned int g_count = 0;

// ---- packed f32x2 helpers (sm_100+; ptxas won't auto-fuse, must be PTX) ----
__device__ __forceinline__ unsigned long long pack2(float a, float b) {
    unsigned long long r;
    asm("mov.b64 %0, {%1, %2};" : "=l"(r) : "f"(a), "f"(b));
    return r;
}
__device__ __forceinline__ unsigned long long fma2(unsigned long long a,
                                                   unsigned long long b,
                                                   unsigned long long c) {
    unsigned long long d;
    asm("fma.rn.f32x2 %0, %1, %2, %3;" : "=l"(d) : "l"(a), "l"(b), "l"(c));
    return d;
}
__device__ __forceinline__ void unpack2(unsigned long long v, float& lo, float& hi) {
    asm("mov.b64 {%0, %1}, %2;" : "=f"(lo), "=f"(hi) : "l"(v));
}

// Shared layout: per point-pair p (points 2p, 2p+1), 32 bytes:
//   float8 = { x0,x1, y0,y1, z0,z1, -h0,-h1 }   (h = 0.5*||pt||^2, stored negated)
// read in the hot loop as two ulonglong2 (each LDS.128, uniform idx -> broadcast):
//   v0 = { (x0,x1), (y0,y1) }   v1 = { (z0,z1), (-h0,-h1) }
// Inner math per pair: t2 = fma2(Pz2, z2, nh2); fma2(Py2,y2,t2); fma2(Px2,x2,t2)
// then 2 scalar FMNMX into lo/hi max accumulators.

__global__ void __launch_bounds__(TPB, 1)
chamfer_kernel(const float* __restrict__ x, const float* __restrict__ y,
               float* __restrict__ out) {
    __shared__ ulonglong2 sx2[NPTS];   // 2 entries per pair -> 16KB
    __shared__ ulonglong2 sy2[NPTS];   // 16KB

    const int bt    = blockIdx.x / CHUNKS;
    const int chunk = blockIdx.x % CHUNKS;
    const float* xb = x + (size_t)bt * NPTS * 3;
    const float* yb = y + (size_t)bt * NPTS * 3;

    float* fx = (float*)sx2;
    float* fy = (float*)sy2;

    // Stage with pair-interleaved packed layout.
    for (int p = threadIdx.x; p < NPTS; p += TPB) {
        const int pr = p >> 1, s = p & 1, base = 8 * pr + s;
        float a0 = xb[3 * p + 0], a1 = xb[3 * p + 1], a2 = xb[3 * p + 2];
        fx[base + 0] = a0;
        fx[base + 2] = a1;
        fx[base + 4] = a2;
        fx[base + 6] = -0.5f * (a0 * a0 + a1 * a1 + a2 * a2);

        float b0 = yb[3 * p + 0], b1 = yb[3 * p + 1], b2 = yb[3 * p + 2];
        fy[base + 0] = b0;
        fy[base + 2] = b1;
        fy[base + 4] = b2;
        fy[base + 6] = -0.5f * (b0 * b0 + b1 * b1 + b2 * b2);
    }
    __syncthreads();

    // This thread's own x-point P and y-point Q (scalar reads from smem).
    const int pid = chunk * TPB + threadIdx.x;
    const int pr = pid >> 1, s = pid & 1;
    const float Px = fx[8 * pr + 0 + s], Py = fx[8 * pr + 2 + s],
                Pz = fx[8 * pr + 4 + s], Pnh = fx[8 * pr + 6 + s];
    const float Qx = fy[8 * pr + 0 + s], Qy = fy[8 * pr + 2 + s],
                Qz = fy[8 * pr + 4 + s], Qnh = fy[8 * pr + 6 + s];

    const unsigned long long Px2 = pack2(Px, Px), Py2 = pack2(Py, Py),
                             Pz2 = pack2(Pz, Pz);
    const unsigned long long Qx2 = pack2(Qx, Qx), Qy2 = pack2(Qy, Qy),
                             Qz2 = pack2(Qz, Qz);

    float m1lo = -INFINITY, m1hi = -INFINITY;   // max of (P.y_i - 0.5||y_i||^2)
    float m2lo = -INFINITY, m2hi = -INFINITY;   // max of (Q.x_j - 0.5||x_j||^2)

#pragma unroll 4
    for (int p = 0; p < NPAIRS; ++p) {
        ulonglong2 ya = sy2[2 * p];       // {(x0,x1),(y0,y1)}
        ulonglong2 yb2 = sy2[2 * p + 1];  // {(z0,z1),(-h0,-h1)}
        unsigned long long t = fma2(Pz2, yb2.x, yb2.y);
        t = fma2(Py2, ya.y, t);
        t = fma2(Px2, ya.x, t);
        float tlo, thi;
        unpack2(t, tlo, thi);
        m1lo = fmaxf(m1lo, tlo);
        m1hi = fmaxf(m1hi, thi);

        ulonglong2 xa = sx2[2 * p];
        ulonglong2 xb2v = sx2[2 * p + 1];
        unsigned long long u = fma2(Qz2, xb2v.x, xb2v.y);
        u = fma2(Qy2, xa.y, u);
        u = fma2(Qx2, xa.x, u);
        float ulo, uhi;
        unpack2(u, ulo, uhi);
        m2lo = fmaxf(m2lo, ulo);
        m2hi = fmaxf(m2hi, uhi);
    }

    const float m1 = fmaxf(m1lo, m1hi);
    const float m2 = fmaxf(m2lo, m2hi);
    // min_i sq = 2*(0.5||P||^2 - m1) = -2*(Pnh + m1); clamp, sqrt(EPS + .).
    const float sq1 = fmaxf(-2.0f * (Pnh + m1), 0.0f);
    const float sq2 = fmaxf(-2.0f * (Qnh + m2), 0.0f);
    float contrib = sqrtf(EPS + sq1) + sqrtf(EPS + sq2);

    // Block reduction.
    __shared__ float warp_sums[TPB / 32];
#pragma unroll
    for (int off = 16; off > 0; off >>= 1)
        contrib += __shfl_down_sync(0xFFFFFFFFu, contrib, off);
    if ((threadIdx.x & 31) == 0) warp_sums[threadIdx.x >> 5] = contrib;
    __syncthreads();

    __shared__ bool is_last;
    if (threadIdx.x == 0) {
        float ssum = 0.0f;
#pragma unroll
        for (int w = 0; w < TPB / 32; ++w) ssum += warp_sums[w];
        g_partials[blockIdx.x] = ssum;
        __threadfence();
        unsigned int done = atomicAdd(&g_count, 1u);
        is_last = (done == NBLOCKS - 1);
    }
    __syncthreads();

    // Last block performs the deterministic final reduction (fixed order).
    if (is_last) {
        __threadfence();
        float v = (threadIdx.x < NBLOCKS)
                      ? ((volatile float*)g_partials)[threadIdx.x]
                      : 0.0f;
#pragma unroll
        for (int off = 16; off > 0; off >>= 1)
            v += __shfl_down_sync(0xFFFFFFFFu, v, off);
        if ((threadIdx.x & 31) == 0) warp_sums[threadIdx.x >> 5] = v;
        __syncthreads();
        if (threadIdx.x == 0) {
            float ssum = 0.0f;
#pragma unroll
            for (int w = 0; w < TPB / 32; ++w) ssum += warp_sums[w];
            out[0] = ssum * (1.0f / (float)(BT * NPTS));
            g_count = 0;  // reset for next graph replay
        }
    }
}

extern "C" void kernel_launch(void* const* d_in, const int* in_sizes, int n_in,
                              void* d_out, int out_size) {
    const float* x = (const float*)d_in[0];
    const float* y = (const float*)d_in[1];
    float* out = (float*)d_out;
    (void)in_sizes; (void)n_in; (void)out_size;

    chamfer_kernel<<<NBLOCKS, TPB>>>(x, y, out);
}